// round 8
// baseline (speedup 1.0000x reference)
#include <cuda_runtime.h>
#include <cuda_fp16.h>
#include <math.h>
#include <stdint.h>

#define BATCH   16384
#define D_IN    128
#define HID     16
#define N_INNER 255
#define N_LEAF  256
#define DEPTH   8

#define NCOLS   4096
#define MT      128
#define NTILE   128
#define NT      32
#define GT      512

// ---------------- scratch ----------------
__device__ __half g_xh[BATCH * D_IN];
__device__ __half g_wh[NCOLS * D_IN];

// ---------------- PTX helpers ----------------
#define CP16(dst, src) \
    asm volatile("cp.async.cg.shared.global [%0], [%1], 16;" :: "r"(dst), "l"(src))
#define CP_COMMIT() asm volatile("cp.async.commit_group;" ::: "memory")
#define CP_WAIT0()  asm volatile("cp.async.wait_group 0;" ::: "memory")
#define CP_WAIT1()  asm volatile("cp.async.wait_group 1;" ::: "memory")

#define BARG(id) asm volatile("bar.sync %0, 256;" :: "r"(id) : "memory")

#define LDSM4(R, addr) \
    asm volatile("ldmatrix.sync.aligned.m8n8.x4.shared.b16 {%0,%1,%2,%3}, [%4];" \
                 : "=r"((R)[0]), "=r"((R)[1]), "=r"((R)[2]), "=r"((R)[3]) : "r"(addr))

#define MMA16816(C, A, B0, B1) \
    asm volatile("mma.sync.aligned.m16n8k16.row.col.f32.f16.f16.f32 " \
                 "{%0,%1,%2,%3}, {%4,%5,%6,%7}, {%8,%9}, {%0,%1,%2,%3};" \
                 : "+f"((C)[0]), "+f"((C)[1]), "+f"((C)[2]), "+f"((C)[3]) \
                 : "r"((A)[0]), "r"((A)[1]), "r"((A)[2]), "r"((A)[3]), \
                   "r"(B0), "r"(B1))

__device__ __forceinline__ uint32_t sw_off(int r, int j) {
    return (uint32_t)(r * 256 + (((j & 8) | ((j ^ r) & 7)) << 4));
}

// ---------------- prep kernels ----------------
__global__ void cvt_x_kernel(const float* __restrict__ x) {
    int i = blockIdx.x * 256 + threadIdx.x;
    g_xh[i] = __float2half(x[i]);
}

__global__ void cvt_w_kernel(const float* __restrict__ W1) {
    __shared__ float s[128 * 17 + 16];
    const int n   = blockIdx.x;
    const int tid = threadIdx.x;
    if (n < N_INNER) {
        for (int t = tid; t < 2048; t += 256) {
            int k = t >> 4, h = t & 15;
            s[k * 17 + h] = W1[n * 2048 + t];
        }
        __syncthreads();
        for (int t = tid; t < 2048; t += 256) {
            int h = t >> 7, k = t & 127;
            g_wh[(n * HID + h) * D_IN + k] = __float2half(s[k * 17 + h]);
        }
    } else {
        for (int t = tid; t < 2048; t += 256)
            g_wh[n * HID * D_IN + t] = __float2half(0.f);
    }
}

// ---------------- SMEM layout ----------------
// A 32K @0 ; B 4 bufs x 32K @32768 (buf index = grp*2+parity) ; bw 32K @163840 ;
// ptile 2 x 4K @196608 ; b2 1K @204800
#define SM_A   0
#define SM_B   32768
#define SM_BW  163840
#define SM_PT  196608
#define SM_B2  204800
#define SMEM_TOTAL (204800 + 1024)

__device__ __forceinline__ void load_B_grp(uint32_t dst, const __half* src, int tidg) {
    #pragma unroll
    for (int it = 0; it < 8; it++) {
        int c = tidg + it * 256;         // 0..2047 chunks
        int r = c >> 4, j = c & 15;
        CP16(dst + sw_off(r, j), src + r * D_IN + j * 8);
    }
}

__global__ __launch_bounds__(GT, 1)
void gemm_mma_kernel(const float* __restrict__ b1, const float* __restrict__ W2,
                     const float* __restrict__ b2, float* __restrict__ out)
{
    extern __shared__ char smem[];
    uint32_t sb = (uint32_t)__cvta_generic_to_shared(smem);
    float2* bwS = (float2*)(smem + SM_BW);
    float*  b2S = (float*)(smem + SM_B2);

    const int tid  = threadIdx.x;
    const int lane = tid & 31;
    const int wid  = tid >> 5;
    const int grp  = tid >> 8;           // 0 or 1
    const int tidg = tid & 255;
    const int wig  = wid & 7;            // warp in group
    const int warp_m    = wig & 3;       // 32-row slice
    const int warp_half = wig >> 2;      // 0: cols 0-63, 1: cols 64-127
    const int row0 = blockIdx.x * MT;
    const int barid = 1 + grp;

    float* ptg = (float*)(smem + SM_PT + grp * 4096);   // [128][8]

    // ---- prologue ----
    // A: all 512 threads, 4 chunks each
    #pragma unroll
    for (int it = 0; it < 4; it++) {
        int c = tid + it * GT;
        int r = c >> 4, j = c & 15;
        CP16(sb + SM_A + sw_off(r, j), g_xh + (size_t)(row0 + r) * D_IN + j * 8);
    }
    // B tile (grp) -> buf (grp,0)
    load_B_grp(sb + SM_B + (uint32_t)(grp * 2) * 32768u,
               g_wh + (size_t)grp * NTILE * D_IN, tidg);
    CP_COMMIT();

    for (int i = tid; i < NCOLS; i += GT) {
        float bb = (i < N_INNER * HID) ? b1[i] : 0.f;
        float ww = (i < N_INNER * HID) ? W2[i] : 0.f;
        bwS[i] = make_float2(bb, ww);
    }
    if (tid < 256) b2S[tid] = (tid < N_INNER) ? b2[tid] : 0.f;

    CP_WAIT0();
    __syncthreads();     // A + both B0 + bwS + b2S visible block-wide

    // prefetch tile grp+2 -> buf (grp,1)
    load_B_grp(sb + SM_B + (uint32_t)(grp * 2 + 1) * 32768u,
               g_wh + (size_t)(grp + 2) * NTILE * D_IN, tidg);
    CP_COMMIT();

    const int ra_base = warp_m * 32 + (lane & 7) + ((lane >> 3) & 1) * 8;
    const int ja_add  = lane >> 4;
    const int rb_base = warp_half * 64 + (lane & 7) + ((lane >> 4) & 1) * 8;  // + pr*16
    const int jb_add  = (lane >> 3) & 1;
    const int q  = lane >> 2;
    const int gl = lane & 3;

    float* outp = out + (size_t)BATCH * 257;

    for (int it = 0; it < 16; it++) {
        const int nt  = grp + 2 * it;
        const int cur = it & 1;
        const uint32_t bB = sb + SM_B + (uint32_t)(grp * 2 + cur) * 32768u;

        if (it == 15) { CP_WAIT0(); } else { CP_WAIT1(); }
        BARG(barid);    // tile nt data visible to group; ptile reusable

        float c[16][4];
        #pragma unroll
        for (int f = 0; f < 16; f++)
            #pragma unroll
            for (int e = 0; e < 4; e++) c[f][e] = 0.f;

        #pragma unroll
        for (int ks = 0; ks < 8; ks++) {
            const int j0 = ks * 2;
            uint32_t a0[4], a1[4];
            LDSM4(a0, sb + SM_A + sw_off(ra_base,      j0 + ja_add));
            LDSM4(a1, sb + SM_A + sw_off(ra_base + 16, j0 + ja_add));
            #pragma unroll
            for (int pr = 0; pr < 4; pr++) {
                uint32_t bf[4];
                LDSM4(bf, bB + sw_off(rb_base + pr * 16, j0 + jb_add));
                #pragma unroll
                for (int h = 0; h < 2; h++) {
                    MMA16816(c[0 * 8 + pr * 2 + h], a0, bf[2 * h], bf[2 * h + 1]);
                    MMA16816(c[1 * 8 + pr * 2 + h], a1, bf[2 * h], bf[2 * h + 1]);
                }
            }
        }

        BARG(barid);    // group done reading buf cur

        if (it <= 13) {
            load_B_grp(bB, g_wh + (size_t)(nt + 4) * NTILE * D_IN, tidg);
            CP_COMMIT();
        }

        // ---- epilogue ----
        #pragma unroll
        for (int m = 0; m < 2; m++) {
            #pragma unroll
            for (int nd = 0; nd < 4; nd++) {
                float s0 = 0.f, s1 = 0.f;
                #pragma unroll
                for (int h = 0; h < 2; h++) {
                    int fb = m * 8 + nd * 2 + h;
                    int gcol = nt * 128 + warp_half * 64 + (nd * 2 + h) * 8 + 2 * gl;
                    float2 bw0 = bwS[gcol];
                    float2 bw1 = bwS[gcol + 1];
                    s0 += fmaxf(c[fb][0] + bw0.x, 0.f) * bw0.y + fmaxf(c[fb][1] + bw1.x, 0.f) * bw1.y;
                    s1 += fmaxf(c[fb][2] + bw0.x, 0.f) * bw0.y + fmaxf(c[fb][3] + bw1.x, 0.f) * bw1.y;
                }
                s0 += __shfl_xor_sync(0xffffffffu, s0, 1);
                s0 += __shfl_xor_sync(0xffffffffu, s0, 2);
                s1 += __shfl_xor_sync(0xffffffffu, s1, 1);
                s1 += __shfl_xor_sync(0xffffffffu, s1, 2);
                if (gl == nd) {
                    int nodecol = warp_half * 4 + nd;
                    float b2v = b2S[nt * 8 + nodecol];
                    int r0 = warp_m * 32 + m * 16 + q;
                    ptg[r0 * 8 + nodecol]       = 1.f / (1.f + expf(-(s0 + b2v)));
                    ptg[(r0 + 8) * 8 + nodecol] = 1.f / (1.f + expf(-(s1 + b2v)));
                }
            }
        }
        BARG(barid);

        // coalesced p write (group-local ptile)
        #pragma unroll
        for (int i2 = 0; i2 < 4; i2++) {
            int i = tidg + i2 * 256;     // 0..1023
            int r = i >> 3, cl = i & 7;
            int ng = nt * 8 + cl;
            if (ng < N_INNER)
                outp[(size_t)(row0 + r) * N_INNER + ng] = ptg[i];
        }
    }
}

// ---------------- Kernel 2: tree pass, shuffle-only ----------------
#define THREADS2 512

__global__ __launch_bounds__(THREADS2, 1)
void tree_kernel(const float* __restrict__ leaf, float* __restrict__ out)
{
    const int tid  = threadIdx.x;
    const int wid  = tid >> 5;
    const int lane = tid & 31;
    const int row  = blockIdx.x * 16 + wid;

    const float* prow = out + (size_t)BATCH * 257 + (size_t)row * N_INNER;
    float* nr = out + (size_t)BATCH * 512 + (size_t)row * N_INNER;
    float* pp = out + (size_t)BATCH + (size_t)row * N_LEAF;

    float pl[5];
    #pragma unroll
    for (int l = 0; l < 5; l++) {
        const int sz = 1 << l;
        pl[l] = (lane < sz) ? __ldg(prow + sz - 1 + lane) : 0.f;
    }
    float p5  = __ldg(prow + 31 + lane);
    float p6a = __ldg(prow + 63 + 2 * lane);
    float p6b = __ldg(prow + 63 + 2 * lane + 1);
    float p7[4];
    #pragma unroll
    for (int j = 0; j < 4; j++) p7[j] = __ldg(prow + 127 + 4 * lane + j);

    const float4* lf4 = (const float4*)(leaf + 8 * lane);
    float4 l0 = lf4[0], l1 = lf4[1];

    float rv = (lane == 0) ? 1.f : 0.f;
    #pragma unroll
    for (int l = 0; l < 5; l++) {
        const int sz = 1 << l;
        if (lane < sz) nr[sz - 1 + lane] = rv;
        float rp = __shfl_sync(0xffffffffu, rv, lane >> 1);
        float pq = __shfl_sync(0xffffffffu, pl[l], lane >> 1);
        rv = (lane & 1) ? rp * pq : rp * (1.f - pq);
    }

    nr[31 + lane] = rv;
    float r6a = rv * (1.f - p5);
    float r6b = rv * p5;

    nr[63 + 2 * lane]     = r6a;
    nr[63 + 2 * lane + 1] = r6b;
    float r7[4] = { r6a * (1.f - p6a), r6a * p6a, r6b * (1.f - p6b), r6b * p6b };

    #pragma unroll
    for (int j = 0; j < 4; j++) nr[127 + 4 * lane + j] = r7[j];

    float r8[8];
    #pragma unroll
    for (int j = 0; j < 4; j++) {
        r8[2 * j]     = r7[j] * (1.f - p7[j]);
        r8[2 * j + 1] = r7[j] * p7[j];
    }
    float4* pp4 = (float4*)(pp + 8 * lane);
    pp4[0] = make_float4(r8[0], r8[1], r8[2], r8[3]);
    pp4[1] = make_float4(r8[4], r8[5], r8[6], r8[7]);

    float hs = r8[0] * l0.x + r8[1] * l0.y + r8[2] * l0.z + r8[3] * l0.w
             + r8[4] * l1.x + r8[5] * l1.y + r8[6] * l1.z + r8[7] * l1.w;
    #pragma unroll
    for (int o = 16; o; o >>= 1) hs += __shfl_down_sync(0xffffffffu, hs, o);
    if (lane == 0) out[row] = hs;
}

// ---------------- launch ----------------
extern "C" void kernel_launch(void* const* d_in, const int* in_sizes, int n_in,
                              void* d_out, int out_size)
{
    const float* x    = (const float*)d_in[0];
    const float* W1   = (const float*)d_in[1];
    const float* b1   = (const float*)d_in[2];
    const float* W2   = (const float*)d_in[3];
    const float* b2   = (const float*)d_in[4];
    const float* leaf = (const float*)d_in[5];
    float* out = (float*)d_out;

    cvt_x_kernel<<<(BATCH * D_IN) / 256, 256>>>(x);
    cvt_w_kernel<<<256, 256>>>(W1);

    cudaFuncSetAttribute(gemm_mma_kernel, cudaFuncAttributeMaxDynamicSharedMemorySize, SMEM_TOTAL);
    gemm_mma_kernel<<<BATCH / MT, GT, SMEM_TOTAL>>>(b1, W2, b2, out);

    tree_kernel<<<BATCH / 16, THREADS2>>>(leaf, out);
}

// round 13
// speedup vs baseline: 1.2355x; 1.2355x over previous
#include <cuda_runtime.h>
#include <cuda_fp16.h>
#include <math.h>
#include <stdint.h>

#define BATCH   16384
#define D_IN    128
#define HID     16
#define N_INNER 255
#define N_LEAF  256
#define DEPTH   8

#define NCOLS   4096
#define MT      128
#define NTILE   128
#define NT      32
#define GT      512

// ---------------- scratch ----------------
__device__ __half g_xh[BATCH * D_IN];
__device__ __half g_wh[NCOLS * D_IN];

// ---------------- PTX helpers ----------------
#define CP16(dst, src) \
    asm volatile("cp.async.cg.shared.global [%0], [%1], 16;" :: "r"(dst), "l"(src))
#define CP_COMMIT() asm volatile("cp.async.commit_group;" ::: "memory")
#define CP_WAIT0()  asm volatile("cp.async.wait_group 0;" ::: "memory")

#define LDSM4(R, addr) \
    asm volatile("ldmatrix.sync.aligned.m8n8.x4.shared.b16 {%0,%1,%2,%3}, [%4];" \
                 : "=r"((R)[0]), "=r"((R)[1]), "=r"((R)[2]), "=r"((R)[3]) : "r"(addr))

#define MMA16816(C, A, B0, B1) \
    asm volatile("mma.sync.aligned.m16n8k16.row.col.f32.f16.f16.f32 " \
                 "{%0,%1,%2,%3}, {%4,%5,%6,%7}, {%8,%9}, {%0,%1,%2,%3};" \
                 : "+f"((C)[0]), "+f"((C)[1]), "+f"((C)[2]), "+f"((C)[3]) \
                 : "r"((A)[0]), "r"((A)[1]), "r"((A)[2]), "r"((A)[3]), \
                   "r"(B0), "r"(B1))

// XOR swizzle for a 128x128-f16 tile (256 B rows, 16B chunks)
__device__ __forceinline__ uint32_t sw_off(int r, int j) {
    return (uint32_t)(r * 256 + (((j & 8) | ((j ^ r) & 7)) << 4));
}

// ---------------- prep kernels ----------------
__global__ void cvt_x_kernel(const float* __restrict__ x) {
    int i = blockIdx.x * 256 + threadIdx.x;
    g_xh[i] = __float2half(x[i]);
}

// W1 [255][128 k][16 h] f32  ->  g_wh [(n,h) col][k] f16, via smem transpose.
__global__ void cvt_w_kernel(const float* __restrict__ W1) {
    __shared__ float s[128 * 17 + 16];
    const int n   = blockIdx.x;
    const int tid = threadIdx.x;
    if (n < N_INNER) {
        for (int t = tid; t < 2048; t += 256) {
            int k = t >> 4, h = t & 15;
            s[k * 17 + h] = W1[n * 2048 + t];
        }
        __syncthreads();
        for (int t = tid; t < 2048; t += 256) {
            int h = t >> 7, k = t & 127;
            g_wh[(n * HID + h) * D_IN + k] = __float2half(s[k * 17 + h]);
        }
    } else {
        for (int t = tid; t < 2048; t += 256)
            g_wh[n * HID * D_IN + t] = __float2half(0.f);
    }
}

// ---------------- SMEM layout (fits 2 CTAs/SM: 100 KB) ----------------
// A(xh) 32KB @0 ; B 2 bufs x 32KB @32768 ; ptile 4KB @98304
#define SM_A   0
#define SM_B   32768
#define SM_PT  98304
#define SMEM_TOTAL (98304 + 4096)

__device__ __forceinline__ void load_tile(uint32_t dst, const __half* src, int tid) {
    #pragma unroll
    for (int it = 0; it < 4; it++) {
        int c = tid + it * GT;           // 0..2047 chunks
        int r = c >> 4, j = c & 15;
        CP16(dst + sw_off(r, j), src + r * D_IN + j * 8);
    }
}

__global__ __launch_bounds__(GT, 2)
void gemm_mma_kernel(const float* __restrict__ b1, const float* __restrict__ W2,
                     const float* __restrict__ b2, float* __restrict__ out)
{
    extern __shared__ char smem[];
    uint32_t sb = (uint32_t)__cvta_generic_to_shared(smem);
    float* ptile = (float*)(smem + SM_PT);       // [128][8]

    const int tid    = threadIdx.x;
    const int lane   = tid & 31;
    const int wid    = tid >> 5;
    const int warp_m = wid & 3;                  // 4 x 32 rows
    const int warp_n = wid >> 2;                 // 4 x 32 cols
    const int row0   = blockIdx.x * MT;

    // Preload A and B tile 0
    load_tile(sb + SM_A, g_xh + (size_t)row0 * D_IN, tid);
    load_tile(sb + SM_B, g_wh, tid);
    CP_COMMIT();

    const int ra_base = warp_m * 32 + (lane & 7) + ((lane >> 3) & 1) * 8;  // + mf*16
    const int ja_add  = lane >> 4;
    const int rb_base = warp_n * 32 + (lane & 7) + ((lane >> 4) & 1) * 8;  // + bf*16
    const int jb_add  = (lane >> 3) & 1;

    float* outp = out + (size_t)BATCH * 257;     // p region

    for (int nt = 0; nt < NT; nt++) {
        const int s = nt & 1;

        CP_WAIT0();
        __syncthreads();   // B[s] ready; fences previous ptile readback

        if (nt + 1 < NT) {
            load_tile(sb + SM_B + (uint32_t)(1 - s) * 32768u,
                      g_wh + (size_t)(nt + 1) * NTILE * D_IN, tid);
            CP_COMMIT();
        }

        float c[8][4];
        #pragma unroll
        for (int f = 0; f < 8; f++)
            #pragma unroll
            for (int e = 0; e < 4; e++) c[f][e] = 0.f;

        const uint32_t bB = sb + SM_B + (uint32_t)s * 32768u;

        #pragma unroll
        for (int ks = 0; ks < 8; ks++) {
            const int j0 = ks * 2;
            uint32_t a[2][4], bh[2][4];
            LDSM4(a[0],  sb + SM_A + sw_off(ra_base,      j0 + ja_add));
            LDSM4(a[1],  sb + SM_A + sw_off(ra_base + 16, j0 + ja_add));
            LDSM4(bh[0], bB + sw_off(rb_base,      j0 + jb_add));
            LDSM4(bh[1], bB + sw_off(rb_base + 16, j0 + jb_add));
            #pragma unroll
            for (int mf = 0; mf < 2; mf++)
                #pragma unroll
                for (int bf = 0; bf < 2; bf++)
                    #pragma unroll
                    for (int h = 0; h < 2; h++)
                        MMA16816(c[mf * 4 + bf * 2 + h], a[mf],
                                 bh[bf][2 * h], bh[bf][2 * h + 1]);
        }

        // ---- epilogue: +b1, relu, dot W2, +b2, sigmoid -> ptile ----
        // b1/W2 read straight from global (8 KB, L1/L2-resident).
        const int q = lane >> 2, g = lane & 3;
        #pragma unroll
        for (int m = 0; m < 2; m++) {
            #pragma unroll
            for (int nd = 0; nd < 2; nd++) {
                float s0 = 0.f, s1 = 0.f;
                #pragma unroll
                for (int h = 0; h < 2; h++) {
                    int f = m * 4 + nd * 2 + h;
                    int gcol = nt * 128 + warp_n * 32 + (nd * 2 + h) * 8 + 2 * g;
                    float bb0 = 0.f, ww0 = 0.f, bb1 = 0.f, ww1 = 0.f;
                    if (gcol < N_INNER * HID) {
                        bb0 = __ldg(b1 + gcol);     ww0 = __ldg(W2 + gcol);
                        bb1 = __ldg(b1 + gcol + 1); ww1 = __ldg(W2 + gcol + 1);
                    }
                    s0 += fmaxf(c[f][0] + bb0, 0.f) * ww0 + fmaxf(c[f][1] + bb1, 0.f) * ww1;
                    s1 += fmaxf(c[f][2] + bb0, 0.f) * ww0 + fmaxf(c[f][3] + bb1, 0.f) * ww1;
                }
                s0 += __shfl_xor_sync(0xffffffffu, s0, 1);
                s0 += __shfl_xor_sync(0xffffffffu, s0, 2);
                s1 += __shfl_xor_sync(0xffffffffu, s1, 1);
                s1 += __shfl_xor_sync(0xffffffffu, s1, 2);
                if (g == nd) {
                    int nl = warp_n * 2 + nd;
                    int ng = nt * 8 + nl;
                    float b2v = (ng < N_INNER) ? __ldg(b2 + ng) : 0.f;
                    int r0 = warp_m * 32 + m * 16 + q;
                    ptile[r0 * 8 + nl]       = 1.f / (1.f + expf(-(s0 + b2v)));
                    ptile[(r0 + 8) * 8 + nl] = 1.f / (1.f + expf(-(s1 + b2v)));
                }
            }
        }
        __syncthreads();

        // coalesced p write: 8 consecutive floats per row
        #pragma unroll
        for (int i = tid; i < MT * 8; i += GT) {
            int r = i >> 3, cl = i & 7;
            int ng = nt * 8 + cl;
            if (ng < N_INNER)
                outp[(size_t)(row0 + r) * N_INNER + ng] = ptile[i];
        }
    }
}

// ---------------- Kernel 2: tree pass, shuffle-only (round-7 proven config) ----------
#define THREADS2 256

__global__ __launch_bounds__(THREADS2, 1)
void tree_kernel(const float* __restrict__ leaf, float* __restrict__ out)
{
    const int tid  = threadIdx.x;
    const int wid  = tid >> 5;
    const int lane = tid & 31;
    const int row  = blockIdx.x * 8 + wid;

    const float* prow = out + (size_t)BATCH * 257 + (size_t)row * N_INNER;
    float* nr = out + (size_t)BATCH * 512 + (size_t)row * N_INNER;
    float* pp = out + (size_t)BATCH + (size_t)row * N_LEAF;

    float pl[5];
    #pragma unroll
    for (int l = 0; l < 5; l++) {
        const int sz = 1 << l;
        pl[l] = (lane < sz) ? __ldg(prow + sz - 1 + lane) : 0.f;
    }
    float p5  = __ldg(prow + 31 + lane);
    float p6a = __ldg(prow + 63 + 2 * lane);
    float p6b = __ldg(prow + 63 + 2 * lane + 1);
    float p7[4];
    #pragma unroll
    for (int j = 0; j < 4; j++) p7[j] = __ldg(prow + 127 + 4 * lane + j);

    const float4* lf4 = (const float4*)(leaf + 8 * lane);
    float4 l0 = lf4[0], l1 = lf4[1];

    float rv = (lane == 0) ? 1.f : 0.f;
    #pragma unroll
    for (int l = 0; l < 5; l++) {
        const int sz = 1 << l;
        if (lane < sz) nr[sz - 1 + lane] = rv;
        float rp = __shfl_sync(0xffffffffu, rv, lane >> 1);
        float pq = __shfl_sync(0xffffffffu, pl[l], lane >> 1);
        rv = (lane & 1) ? rp * pq : rp * (1.f - pq);
    }

    nr[31 + lane] = rv;
    float r6a = rv * (1.f - p5);
    float r6b = rv * p5;

    nr[63 + 2 * lane]     = r6a;
    nr[63 + 2 * lane + 1] = r6b;
    float r7[4] = { r6a * (1.f - p6a), r6a * p6a, r6b * (1.f - p6b), r6b * p6b };

    #pragma unroll
    for (int j = 0; j < 4; j++) nr[127 + 4 * lane + j] = r7[j];

    float r8[8];
    #pragma unroll
    for (int j = 0; j < 4; j++) {
        r8[2 * j]     = r7[j] * (1.f - p7[j]);
        r8[2 * j + 1] = r7[j] * p7[j];
    }
    float4* pp4 = (float4*)(pp + 8 * lane);
    pp4[0] = make_float4(r8[0], r8[1], r8[2], r8[3]);
    pp4[1] = make_float4(r8[4], r8[5], r8[6], r8[7]);

    float hs = r8[0] * l0.x + r8[1] * l0.y + r8[2] * l0.z + r8[3] * l0.w
             + r8[4] * l1.x + r8[5] * l1.y + r8[6] * l1.z + r8[7] * l1.w;
    #pragma unroll
    for (int o = 16; o; o >>= 1) hs += __shfl_down_sync(0xffffffffu, hs, o);
    if (lane == 0) out[row] = hs;
}

// ---------------- launch ----------------
extern "C" void kernel_launch(void* const* d_in, const int* in_sizes, int n_in,
                              void* d_out, int out_size)
{
    const float* x    = (const float*)d_in[0];
    const float* W1   = (const float*)d_in[1];
    const float* b1   = (const float*)d_in[2];
    const float* W2   = (const float*)d_in[3];
    const float* b2   = (const float*)d_in[4];
    const float* leaf = (const float*)d_in[5];
    float* out = (float*)d_out;

    cvt_x_kernel<<<(BATCH * D_IN) / 256, 256>>>(x);
    cvt_w_kernel<<<256, 256>>>(W1);

    cudaFuncSetAttribute(gemm_mma_kernel, cudaFuncAttributeMaxDynamicSharedMemorySize, SMEM_TOTAL);
    gemm_mma_kernel<<<BATCH / MT, GT, SMEM_TOTAL>>>(b1, W2, b2, out);

    tree_kernel<<<BATCH / 8, THREADS2>>>(leaf, out);
}

// round 14
// speedup vs baseline: 1.3234x; 1.0711x over previous
#include <cuda_runtime.h>
#include <cuda_fp16.h>
#include <math.h>
#include <stdint.h>

#define BATCH   16384
#define D_IN    128
#define HID     16
#define N_INNER 255
#define N_LEAF  256
#define DEPTH   8

#define NCOLS   4096
#define MT      64     // rows per CTA  -> grid 256, 2 CTAs/SM
#define NTILE   128
#define NT      32
#define GT      256    // 8 warps: 2(m) x 4(n)

// ---------------- scratch ----------------
__device__ __half g_xh[BATCH * D_IN];
__device__ __half g_wh[NCOLS * D_IN];

// ---------------- PTX helpers ----------------
#define CP16(dst, src) \
    asm volatile("cp.async.cg.shared.global [%0], [%1], 16;" :: "r"(dst), "l"(src))
#define CP_COMMIT() asm volatile("cp.async.commit_group;" ::: "memory")
#define CP_WAIT0()  asm volatile("cp.async.wait_group 0;" ::: "memory")

#define LDSM4(R, addr) \
    asm volatile("ldmatrix.sync.aligned.m8n8.x4.shared.b16 {%0,%1,%2,%3}, [%4];" \
                 : "=r"((R)[0]), "=r"((R)[1]), "=r"((R)[2]), "=r"((R)[3]) : "r"(addr))

#define MMA16816(C, A, B0, B1) \
    asm volatile("mma.sync.aligned.m16n8k16.row.col.f32.f16.f16.f32 " \
                 "{%0,%1,%2,%3}, {%4,%5,%6,%7}, {%8,%9}, {%0,%1,%2,%3};" \
                 : "+f"((C)[0]), "+f"((C)[1]), "+f"((C)[2]), "+f"((C)[3]) \
                 : "r"((A)[0]), "r"((A)[1]), "r"((A)[2]), "r"((A)[3]), \
                   "r"(B0), "r"(B1))

// XOR swizzle for 256 B rows, 16B chunks
__device__ __forceinline__ uint32_t sw_off(int r, int j) {
    return (uint32_t)(r * 256 + (((j & 8) | ((j ^ r) & 7)) << 4));
}

// ---------------- prep kernels ----------------
__global__ void cvt_x_kernel(const float* __restrict__ x) {
    int i = blockIdx.x * 256 + threadIdx.x;
    g_xh[i] = __float2half(x[i]);
}

// W1 [255][128 k][16 h] f32  ->  g_wh [(n,h) col][k] f16, via smem transpose.
__global__ void cvt_w_kernel(const float* __restrict__ W1) {
    __shared__ float s[128 * 17 + 16];
    const int n   = blockIdx.x;
    const int tid = threadIdx.x;
    if (n < N_INNER) {
        for (int t = tid; t < 2048; t += 256) {
            int k = t >> 4, h = t & 15;
            s[k * 17 + h] = W1[n * 2048 + t];
        }
        __syncthreads();
        for (int t = tid; t < 2048; t += 256) {
            int h = t >> 7, k = t & 127;
            g_wh[(n * HID + h) * D_IN + k] = __float2half(s[k * 17 + h]);
        }
    } else {
        for (int t = tid; t < 2048; t += 256)
            g_wh[n * HID * D_IN + t] = __float2half(0.f);
    }
}

// ---------------- SMEM layout: 84 KB -> 2 CTAs/SM ----------------
// A(xh) 16KB @0 ; B 2 bufs x 32KB @16384 ; ptile 2KB @81920
#define SM_A   0
#define SM_B   16384
#define SM_PT  81920
#define SMEM_TOTAL (81920 + 2048)

__device__ __forceinline__ void load_B_tile(uint32_t dst, const __half* src, int tid) {
    #pragma unroll
    for (int it = 0; it < 8; it++) {
        int c = tid + it * GT;           // 0..2047 chunks
        int r = c >> 4, j = c & 15;
        CP16(dst + sw_off(r, j), src + r * D_IN + j * 8);
    }
}

__global__ __launch_bounds__(GT)
void gemm_mma_kernel(const float* __restrict__ b1, const float* __restrict__ W2,
                     const float* __restrict__ b2, float* __restrict__ out)
{
    extern __shared__ char smem[];
    uint32_t sb = (uint32_t)__cvta_generic_to_shared(smem);
    float* ptile = (float*)(smem + SM_PT);       // [64][8]

    const int tid    = threadIdx.x;
    const int lane   = tid & 31;
    const int wid    = tid >> 5;
    const int warp_m = wid & 1;                  // 2 x 32 rows
    const int warp_n = wid >> 1;                 // 4 x 32 cols
    const int row0   = blockIdx.x * MT;

    // Preload A (64 rows = 1024 chunks) and B tile 0
    #pragma unroll
    for (int it = 0; it < 4; it++) {
        int c = tid + it * GT;
        int r = c >> 4, j = c & 15;
        CP16(sb + SM_A + sw_off(r, j), g_xh + (size_t)(row0 + r) * D_IN + j * 8);
    }
    load_B_tile(sb + SM_B, g_wh, tid);
    CP_COMMIT();

    const int ra_base = warp_m * 32 + (lane & 7) + ((lane >> 3) & 1) * 8;  // + mf*16
    const int ja_add  = lane >> 4;
    const int rb_base = warp_n * 32 + (lane & 7) + ((lane >> 4) & 1) * 8;  // + bf*16
    const int jb_add  = (lane >> 3) & 1;

    float* outp = out + (size_t)BATCH * 257;     // p region

    for (int nt = 0; nt < NT; nt++) {
        const int s = nt & 1;

        CP_WAIT0();
        __syncthreads();   // B[s] ready; fences previous ptile readback

        if (nt + 1 < NT) {
            load_B_tile(sb + SM_B + (uint32_t)(1 - s) * 32768u,
                        g_wh + (size_t)(nt + 1) * NTILE * D_IN, tid);
            CP_COMMIT();
        }

        float c[8][4];
        #pragma unroll
        for (int f = 0; f < 8; f++)
            #pragma unroll
            for (int e = 0; e < 4; e++) c[f][e] = 0.f;

        const uint32_t bB = sb + SM_B + (uint32_t)s * 32768u;

        #pragma unroll
        for (int ks = 0; ks < 8; ks++) {
            const int j0 = ks * 2;
            uint32_t a[2][4], bh[2][4];
            LDSM4(a[0],  sb + SM_A + sw_off(ra_base,      j0 + ja_add));
            LDSM4(a[1],  sb + SM_A + sw_off(ra_base + 16, j0 + ja_add));
            LDSM4(bh[0], bB + sw_off(rb_base,      j0 + jb_add));
            LDSM4(bh[1], bB + sw_off(rb_base + 16, j0 + jb_add));
            #pragma unroll
            for (int mf = 0; mf < 2; mf++)
                #pragma unroll
                for (int bf = 0; bf < 2; bf++)
                    #pragma unroll
                    for (int h = 0; h < 2; h++)
                        MMA16816(c[mf * 4 + bf * 2 + h], a[mf],
                                 bh[bf][2 * h], bh[bf][2 * h + 1]);
        }

        // ---- epilogue: +b1, relu, dot W2, +b2, sigmoid -> ptile ----
        const int q = lane >> 2, g = lane & 3;
        #pragma unroll
        for (int m = 0; m < 2; m++) {
            #pragma unroll
            for (int nd = 0; nd < 2; nd++) {
                float s0 = 0.f, s1 = 0.f;
                #pragma unroll
                for (int h = 0; h < 2; h++) {
                    int f = m * 4 + nd * 2 + h;
                    int gcol = nt * 128 + warp_n * 32 + (nd * 2 + h) * 8 + 2 * g;
                    float bb0 = 0.f, ww0 = 0.f, bb1 = 0.f, ww1 = 0.f;
                    if (gcol < N_INNER * HID) {
                        bb0 = __ldg(b1 + gcol);     ww0 = __ldg(W2 + gcol);
                        bb1 = __ldg(b1 + gcol + 1); ww1 = __ldg(W2 + gcol + 1);
                    }
                    s0 += fmaxf(c[f][0] + bb0, 0.f) * ww0 + fmaxf(c[f][1] + bb1, 0.f) * ww1;
                    s1 += fmaxf(c[f][2] + bb0, 0.f) * ww0 + fmaxf(c[f][3] + bb1, 0.f) * ww1;
                }
                s0 += __shfl_xor_sync(0xffffffffu, s0, 1);
                s0 += __shfl_xor_sync(0xffffffffu, s0, 2);
                s1 += __shfl_xor_sync(0xffffffffu, s1, 1);
                s1 += __shfl_xor_sync(0xffffffffu, s1, 2);
                if (g == nd) {
                    int nl = warp_n * 2 + nd;
                    int ng = nt * 8 + nl;
                    float b2v = (ng < N_INNER) ? __ldg(b2 + ng) : 0.f;
                    int r0 = warp_m * 32 + m * 16 + q;
                    ptile[r0 * 8 + nl]       = 1.f / (1.f + expf(-(s0 + b2v)));
                    ptile[(r0 + 8) * 8 + nl] = 1.f / (1.f + expf(-(s1 + b2v)));
                }
            }
        }
        __syncthreads();

        // coalesced p write: 8 consecutive floats per row (64 rows)
        #pragma unroll
        for (int i2 = 0; i2 < 2; i2++) {
            int i = tid + i2 * GT;       // 0..511
            int r = i >> 3, cl = i & 7;
            int ng = nt * 8 + cl;
            if (ng < N_INNER)
                outp[(size_t)(row0 + r) * N_INNER + ng] = ptile[i];
        }
    }
}

// ---------------- Kernel 2: tree pass, shuffle-only (proven config) ----------
#define THREADS2 256

__global__ __launch_bounds__(THREADS2, 1)
void tree_kernel(const float* __restrict__ leaf, float* __restrict__ out)
{
    const int tid  = threadIdx.x;
    const int wid  = tid >> 5;
    const int lane = tid & 31;
    const int row  = blockIdx.x * 8 + wid;

    const float* prow = out + (size_t)BATCH * 257 + (size_t)row * N_INNER;
    float* nr = out + (size_t)BATCH * 512 + (size_t)row * N_INNER;
    float* pp = out + (size_t)BATCH + (size_t)row * N_LEAF;

    float pl[5];
    #pragma unroll
    for (int l = 0; l < 5; l++) {
        const int sz = 1 << l;
        pl[l] = (lane < sz) ? __ldg(prow + sz - 1 + lane) : 0.f;
    }
    float p5  = __ldg(prow + 31 + lane);
    float p6a = __ldg(prow + 63 + 2 * lane);
    float p6b = __ldg(prow + 63 + 2 * lane + 1);
    float p7[4];
    #pragma unroll
    for (int j = 0; j < 4; j++) p7[j] = __ldg(prow + 127 + 4 * lane + j);

    const float4* lf4 = (const float4*)(leaf + 8 * lane);
    float4 l0 = lf4[0], l1 = lf4[1];

    float rv = (lane == 0) ? 1.f : 0.f;
    #pragma unroll
    for (int l = 0; l < 5; l++) {
        const int sz = 1 << l;
        if (lane < sz) nr[sz - 1 + lane] = rv;
        float rp = __shfl_sync(0xffffffffu, rv, lane >> 1);
        float pq = __shfl_sync(0xffffffffu, pl[l], lane >> 1);
        rv = (lane & 1) ? rp * pq : rp * (1.f - pq);
    }

    nr[31 + lane] = rv;
    float r6a = rv * (1.f - p5);
    float r6b = rv * p5;

    nr[63 + 2 * lane]     = r6a;
    nr[63 + 2 * lane + 1] = r6b;
    float r7[4] = { r6a * (1.f - p6a), r6a * p6a, r6b * (1.f - p6b), r6b * p6b };

    #pragma unroll
    for (int j = 0; j < 4; j++) nr[127 + 4 * lane + j] = r7[j];

    float r8[8];
    #pragma unroll
    for (int j = 0; j < 4; j++) {
        r8[2 * j]     = r7[j] * (1.f - p7[j]);
        r8[2 * j + 1] = r7[j] * p7[j];
    }
    float4* pp4 = (float4*)(pp + 8 * lane);
    pp4[0] = make_float4(r8[0], r8[1], r8[2], r8[3]);
    pp4[1] = make_float4(r8[4], r8[5], r8[6], r8[7]);

    float hs = r8[0] * l0.x + r8[1] * l0.y + r8[2] * l0.z + r8[3] * l0.w
             + r8[4] * l1.x + r8[5] * l1.y + r8[6] * l1.z + r8[7] * l1.w;
    #pragma unroll
    for (int o = 16; o; o >>= 1) hs += __shfl_down_sync(0xffffffffu, hs, o);
    if (lane == 0) out[row] = hs;
}

// ---------------- launch ----------------
extern "C" void kernel_launch(void* const* d_in, const int* in_sizes, int n_in,
                              void* d_out, int out_size)
{
    const float* x    = (const float*)d_in[0];
    const float* W1   = (const float*)d_in[1];
    const float* b1   = (const float*)d_in[2];
    const float* W2   = (const float*)d_in[3];
    const float* b2   = (const float*)d_in[4];
    const float* leaf = (const float*)d_in[5];
    float* out = (float*)d_out;

    cvt_x_kernel<<<(BATCH * D_IN) / 256, 256>>>(x);
    cvt_w_kernel<<<256, 256>>>(W1);

    cudaFuncSetAttribute(gemm_mma_kernel, cudaFuncAttributeMaxDynamicSharedMemorySize, SMEM_TOTAL);
    gemm_mma_kernel<<<BATCH / MT, GT, SMEM_TOTAL>>>(b1, W2, b2, out);

    tree_kernel<<<BATCH / 8, THREADS2>>>(leaf, out);
}

// round 15
// speedup vs baseline: 1.3594x; 1.0273x over previous
#include <cuda_runtime.h>
#include <cuda_fp16.h>
#include <math.h>
#include <stdint.h>

#define BATCH   16384
#define D_IN    128
#define HID     16
#define N_INNER 255
#define N_LEAF  256
#define DEPTH   8

#define NCOLS   4096
#define MT      128
#define NTILE   128
#define NT      32
#define GT      512

// ---------------- scratch ----------------
__device__ __half g_xh[BATCH * D_IN];
__device__ __half g_wh[NCOLS * D_IN];

// ---------------- PTX helpers ----------------
#define CP16(dst, src) \
    asm volatile("cp.async.cg.shared.global [%0], [%1], 16;" :: "r"(dst), "l"(src))
#define CP_COMMIT() asm volatile("cp.async.commit_group;" ::: "memory")
#define CP_WAIT0()  asm volatile("cp.async.wait_group 0;" ::: "memory")

#define LDSM4(R, addr) \
    asm volatile("ldmatrix.sync.aligned.m8n8.x4.shared.b16 {%0,%1,%2,%3}, [%4];" \
                 : "=r"((R)[0]), "=r"((R)[1]), "=r"((R)[2]), "=r"((R)[3]) : "r"(addr))

#define MMA16816(C, A, B0, B1) \
    asm volatile("mma.sync.aligned.m16n8k16.row.col.f32.f16.f16.f32 " \
                 "{%0,%1,%2,%3}, {%4,%5,%6,%7}, {%8,%9}, {%0,%1,%2,%3};" \
                 : "+f"((C)[0]), "+f"((C)[1]), "+f"((C)[2]), "+f"((C)[3]) \
                 : "r"((A)[0]), "r"((A)[1]), "r"((A)[2]), "r"((A)[3]), \
                   "r"(B0), "r"(B1))

// XOR swizzle for 256 B rows, 16B chunks
__device__ __forceinline__ uint32_t sw_off(int r, int j) {
    return (uint32_t)(r * 256 + (((j & 8) | ((j ^ r) & 7)) << 4));
}

// ---------------- prep kernels ----------------
__global__ void cvt_x_kernel(const float* __restrict__ x) {
    int i = blockIdx.x * 256 + threadIdx.x;
    g_xh[i] = __float2half(x[i]);
}

// W1 [255][128 k][16 h] f32  ->  g_wh [(n,h) col][k] f16, via smem transpose.
__global__ void cvt_w_kernel(const float* __restrict__ W1) {
    __shared__ float s[128 * 17 + 16];
    const int n   = blockIdx.x;
    const int tid = threadIdx.x;
    if (n < N_INNER) {
        for (int t = tid; t < 2048; t += 256) {
            int k = t >> 4, h = t & 15;
            s[k * 17 + h] = W1[n * 2048 + t];
        }
        __syncthreads();
        for (int t = tid; t < 2048; t += 256) {
            int h = t >> 7, k = t & 127;
            g_wh[(n * HID + h) * D_IN + k] = __float2half(s[k * 17 + h]);
        }
    } else {
        for (int t = tid; t < 2048; t += 256)
            g_wh[n * HID * D_IN + t] = __float2half(0.f);
    }
}

// ---------------- SMEM layout: 224.5 KB, 1 CTA/SM ----------------
// A(xh) 32KB @0 ; B 2 bufs x 32KB @32768 ; pbuf [128][257] f32 @98304 (131584 B)
#define SM_A   0
#define SM_B   32768
#define SM_P   98304
#define PSTR   257
#define SMEM_TOTAL (98304 + 131584)

__device__ __forceinline__ void load_tile(uint32_t dst, const __half* src, int tid) {
    #pragma unroll
    for (int it = 0; it < 4; it++) {
        int c = tid + it * GT;           // 0..2047 chunks
        int r = c >> 4, j = c & 15;
        CP16(dst + sw_off(r, j), src + r * D_IN + j * 8);
    }
}

__global__ __launch_bounds__(GT, 1)
void gemm_tree_kernel(const float* __restrict__ b1, const float* __restrict__ W2,
                      const float* __restrict__ b2, const float* __restrict__ leaf,
                      float* __restrict__ out)
{
    extern __shared__ char smem[];
    uint32_t sb = (uint32_t)__cvta_generic_to_shared(smem);
    float* pbuf = (float*)(smem + SM_P);         // [128][257]

    const int tid    = threadIdx.x;
    const int lane   = tid & 31;
    const int wid    = tid >> 5;
    const int warp_m = wid & 3;                  // 4 x 32 rows
    const int warp_n = wid >> 2;                 // 4 x 32 cols
    const int row0   = blockIdx.x * MT;

    // Preload A and B tile 0
    load_tile(sb + SM_A, g_xh + (size_t)row0 * D_IN, tid);
    load_tile(sb + SM_B, g_wh, tid);
    CP_COMMIT();

    const int ra_base = warp_m * 32 + (lane & 7) + ((lane >> 3) & 1) * 8;  // + mf*16
    const int ja_add  = lane >> 4;
    const int rb_base = warp_n * 32 + (lane & 7) + ((lane >> 4) & 1) * 8;  // + bf*16
    const int jb_add  = (lane >> 3) & 1;

    float* outp = out + (size_t)BATCH * 257;     // p region

    for (int nt = 0; nt < NT; nt++) {
        const int s = nt & 1;

        CP_WAIT0();
        __syncthreads();   // B[s] ready

        if (nt + 1 < NT) {
            load_tile(sb + SM_B + (uint32_t)(1 - s) * 32768u,
                      g_wh + (size_t)(nt + 1) * NTILE * D_IN, tid);
            CP_COMMIT();
        }

        float c[8][4];
        #pragma unroll
        for (int f = 0; f < 8; f++)
            #pragma unroll
            for (int e = 0; e < 4; e++) c[f][e] = 0.f;

        const uint32_t bB = sb + SM_B + (uint32_t)s * 32768u;

        #pragma unroll
        for (int ks = 0; ks < 8; ks++) {
            const int j0 = ks * 2;
            uint32_t a[2][4], bh[2][4];
            LDSM4(a[0],  sb + SM_A + sw_off(ra_base,      j0 + ja_add));
            LDSM4(a[1],  sb + SM_A + sw_off(ra_base + 16, j0 + ja_add));
            LDSM4(bh[0], bB + sw_off(rb_base,      j0 + jb_add));
            LDSM4(bh[1], bB + sw_off(rb_base + 16, j0 + jb_add));
            #pragma unroll
            for (int mf = 0; mf < 2; mf++)
                #pragma unroll
                for (int bf = 0; bf < 2; bf++)
                    #pragma unroll
                    for (int h = 0; h < 2; h++)
                        MMA16816(c[mf * 4 + bf * 2 + h], a[mf],
                                 bh[bf][2 * h], bh[bf][2 * h + 1]);
        }

        // ---- epilogue: +b1, relu, dot W2, +b2, sigmoid -> pbuf ----
        const int q = lane >> 2, g = lane & 3;
        #pragma unroll
        for (int m = 0; m < 2; m++) {
            #pragma unroll
            for (int nd = 0; nd < 2; nd++) {
                float s0 = 0.f, s1 = 0.f;
                #pragma unroll
                for (int h = 0; h < 2; h++) {
                    int f = m * 4 + nd * 2 + h;
                    int gcol = nt * 128 + warp_n * 32 + (nd * 2 + h) * 8 + 2 * g;
                    float bb0 = 0.f, ww0 = 0.f, bb1 = 0.f, ww1 = 0.f;
                    if (gcol < N_INNER * HID) {
                        bb0 = __ldg(b1 + gcol);     ww0 = __ldg(W2 + gcol);
                        bb1 = __ldg(b1 + gcol + 1); ww1 = __ldg(W2 + gcol + 1);
                    }
                    s0 += fmaxf(c[f][0] + bb0, 0.f) * ww0 + fmaxf(c[f][1] + bb1, 0.f) * ww1;
                    s1 += fmaxf(c[f][2] + bb0, 0.f) * ww0 + fmaxf(c[f][3] + bb1, 0.f) * ww1;
                }
                s0 += __shfl_xor_sync(0xffffffffu, s0, 1);
                s0 += __shfl_xor_sync(0xffffffffu, s0, 2);
                s1 += __shfl_xor_sync(0xffffffffu, s1, 1);
                s1 += __shfl_xor_sync(0xffffffffu, s1, 2);
                if (g == nd) {
                    int nl = warp_n * 2 + nd;
                    int ng = nt * 8 + nl;
                    float b2v = (ng < N_INNER) ? __ldg(b2 + ng) : 0.f;
                    int r0 = warp_m * 32 + m * 16 + q;
                    pbuf[r0 * PSTR + ng]       = 1.f / (1.f + __expf(-(s0 + b2v)));
                    pbuf[(r0 + 8) * PSTR + ng] = 1.f / (1.f + __expf(-(s1 + b2v)));
                }
            }
        }
        __syncthreads();

        // coalesced p write for this tile from pbuf
        #pragma unroll
        for (int i2 = 0; i2 < 2; i2++) {
            int i = tid + i2 * GT;       // 0..1023
            int r = i >> 3, cl = i & 7;
            int ng = nt * 8 + cl;
            if (ng < N_INNER)
                outp[(size_t)(row0 + r) * N_INNER + ng] = pbuf[r * PSTR + ng];
        }
    }

    // ================= fused tree pass (p complete in pbuf) =================
    __syncthreads();

    const float4* lf4 = (const float4*)(leaf + 8 * lane);
    const float4 l0 = lf4[0], l1 = lf4[1];

    #pragma unroll 1
    for (int rr = 0; rr < 8; rr++) {
        const int r   = wid * 8 + rr;            // 0..127
        const int row = row0 + r;
        const float* prow = pbuf + r * PSTR;
        float* nr = out + (size_t)BATCH * 512 + (size_t)row * N_INNER;
        float* pp = out + (size_t)BATCH + (size_t)row * N_LEAF;

        float pl[5];
        #pragma unroll
        for (int l = 0; l < 5; l++) {
            const int sz = 1 << l;
            pl[l] = (lane < sz) ? prow[sz - 1 + lane] : 0.f;
        }
        float p5  = prow[31 + lane];
        float p6a = prow[63 + 2 * lane];
        float p6b = prow[63 + 2 * lane + 1];
        float p7[4];
        #pragma unroll
        for (int j = 0; j < 4; j++) p7[j] = prow[127 + 4 * lane + j];

        float rv = (lane == 0) ? 1.f : 0.f;
        #pragma unroll
        for (int l = 0; l < 5; l++) {
            const int sz = 1 << l;
            if (lane < sz) nr[sz - 1 + lane] = rv;
            float rp = __shfl_sync(0xffffffffu, rv, lane >> 1);
            float pq = __shfl_sync(0xffffffffu, pl[l], lane >> 1);
            rv = (lane & 1) ? rp * pq : rp * (1.f - pq);
        }

        nr[31 + lane] = rv;
        float r6a = rv * (1.f - p5);
        float r6b = rv * p5;

        nr[63 + 2 * lane]     = r6a;
        nr[63 + 2 * lane + 1] = r6b;
        float r7[4] = { r6a * (1.f - p6a), r6a * p6a, r6b * (1.f - p6b), r6b * p6b };

        #pragma unroll
        for (int j = 0; j < 4; j++) nr[127 + 4 * lane + j] = r7[j];

        float r8[8];
        #pragma unroll
        for (int j = 0; j < 4; j++) {
            r8[2 * j]     = r7[j] * (1.f - p7[j]);
            r8[2 * j + 1] = r7[j] * p7[j];
        }
        float4* pp4 = (float4*)(pp + 8 * lane);
        pp4[0] = make_float4(r8[0], r8[1], r8[2], r8[3]);
        pp4[1] = make_float4(r8[4], r8[5], r8[6], r8[7]);

        float hs = r8[0] * l0.x + r8[1] * l0.y + r8[2] * l0.z + r8[3] * l0.w
                 + r8[4] * l1.x + r8[5] * l1.y + r8[6] * l1.z + r8[7] * l1.w;
        #pragma unroll
        for (int o = 16; o; o >>= 1) hs += __shfl_down_sync(0xffffffffu, hs, o);
        if (lane == 0) out[row] = hs;
    }
}

// ---------------- launch ----------------
extern "C" void kernel_launch(void* const* d_in, const int* in_sizes, int n_in,
                              void* d_out, int out_size)
{
    const float* x    = (const float*)d_in[0];
    const float* W1   = (const float*)d_in[1];
    const float* b1   = (const float*)d_in[2];
    const float* W2   = (const float*)d_in[3];
    const float* b2   = (const float*)d_in[4];
    const float* leaf = (const float*)d_in[5];
    float* out = (float*)d_out;

    cvt_x_kernel<<<(BATCH * D_IN) / 256, 256>>>(x);
    cvt_w_kernel<<<256, 256>>>(W1);

    cudaFuncSetAttribute(gemm_tree_kernel, cudaFuncAttributeMaxDynamicSharedMemorySize, SMEM_TOTAL);
    gemm_tree_kernel<<<BATCH / MT, GT, SMEM_TOTAL>>>(b1, W2, b2, leaf, out);
}

// round 16
// speedup vs baseline: 1.3987x; 1.0289x over previous
#include <cuda_runtime.h>
#include <cuda_fp16.h>
#include <math.h>
#include <stdint.h>

#define BATCH   16384
#define D_IN    128
#define HID     16
#define N_INNER 255
#define N_LEAF  256
#define DEPTH   8

#define NCOLS   4096
#define MT      128
#define NTILE   128
#define NT      32
#define GT      512

// ---------------- scratch ----------------
__device__ __half g_xh[BATCH * D_IN];
__device__ __half g_wh[NCOLS * D_IN];

// ---------------- PTX helpers ----------------
#define CP16(dst, src) \
    asm volatile("cp.async.cg.shared.global [%0], [%1], 16;" :: "r"(dst), "l"(src))
#define CP_COMMIT() asm volatile("cp.async.commit_group;" ::: "memory")
#define CP_WAIT0()  asm volatile("cp.async.wait_group 0;" ::: "memory")
#define CP_WAIT1()  asm volatile("cp.async.wait_group 1;" ::: "memory")

#define LDSM4(R, addr) \
    asm volatile("ldmatrix.sync.aligned.m8n8.x4.shared.b16 {%0,%1,%2,%3}, [%4];" \
                 : "=r"((R)[0]), "=r"((R)[1]), "=r"((R)[2]), "=r"((R)[3]) : "r"(addr))

#define MMA16816(C, A, B0, B1) \
    asm volatile("mma.sync.aligned.m16n8k16.row.col.f32.f16.f16.f32 " \
                 "{%0,%1,%2,%3}, {%4,%5,%6,%7}, {%8,%9}, {%0,%1,%2,%3};" \
                 : "+f"((C)[0]), "+f"((C)[1]), "+f"((C)[2]), "+f"((C)[3]) \
                 : "r"((A)[0]), "r"((A)[1]), "r"((A)[2]), "r"((A)[3]), \
                   "r"(B0), "r"(B1))

// XOR swizzle for 256 B rows, 16B chunks
__device__ __forceinline__ uint32_t sw_off(int r, int j) {
    return (uint32_t)(r * 256 + (((j & 8) | ((j ^ r) & 7)) << 4));
}

// ---------------- prep kernels ----------------
__global__ void cvt_x_kernel(const float* __restrict__ x) {
    int i = (blockIdx.x * 256 + threadIdx.x) * 8;
    float4 v0 = *(const float4*)(x + i);
    float4 v1 = *(const float4*)(x + i + 4);
    __half2 h0 = __floats2half2_rn(v0.x, v0.y);
    __half2 h1 = __floats2half2_rn(v0.z, v0.w);
    __half2 h2 = __floats2half2_rn(v1.x, v1.y);
    __half2 h3 = __floats2half2_rn(v1.z, v1.w);
    uint4 o;
    o.x = *(uint32_t*)&h0; o.y = *(uint32_t*)&h1;
    o.z = *(uint32_t*)&h2; o.w = *(uint32_t*)&h3;
    *(uint4*)(g_xh + i) = o;
}

// W1 [255][128 k][16 h] f32  ->  g_wh [(n,h) col][k] f16, via smem transpose.
__global__ void cvt_w_kernel(const float* __restrict__ W1) {
    __shared__ float s[128 * 17 + 16];
    const int n   = blockIdx.x;
    const int tid = threadIdx.x;
    if (n < N_INNER) {
        for (int t = tid; t < 2048; t += 256) {
            int k = t >> 4, h = t & 15;
            s[k * 17 + h] = W1[n * 2048 + t];
        }
        __syncthreads();
        for (int t = tid; t < 2048; t += 256) {
            int h = t >> 7, k = t & 127;
            g_wh[(n * HID + h) * D_IN + k] = __float2half(s[k * 17 + h]);
        }
    } else {
        for (int t = tid; t < 2048; t += 256)
            g_wh[n * HID * D_IN + t] = __float2half(0.f);
    }
}

// ---------------- SMEM layout: 224.5 KB, 1 CTA/SM ----------------
// A(xh) 32KB @0 ; B 2 bufs x 32KB @32768 ; pbuf [128][257] f32 @98304
#define SM_A   0
#define SM_B   32768
#define SM_P   98304
#define PSTR   257
#define SMEM_TOTAL (98304 + 131584)

__device__ __forceinline__ void load_tile(uint32_t dst, const __half* src, int tid) {
    #pragma unroll
    for (int it = 0; it < 4; it++) {
        int c = tid + it * GT;
        int r = c >> 4, j = c & 15;
        CP16(dst + sw_off(r, j), src + r * D_IN + j * 8);
    }
}

__device__ __forceinline__ void mma_tile(uint32_t aB, uint32_t bB, float (*c)[4],
                                         int ra_base, int ja_add, int rb_base, int jb_add)
{
    #pragma unroll
    for (int f = 0; f < 8; f++)
        #pragma unroll
        for (int e = 0; e < 4; e++) c[f][e] = 0.f;

    #pragma unroll
    for (int ks = 0; ks < 8; ks++) {
        const int j0 = ks * 2;
        uint32_t a[2][4], bh[2][4];
        LDSM4(a[0],  aB + sw_off(ra_base,      j0 + ja_add));
        LDSM4(a[1],  aB + sw_off(ra_base + 16, j0 + ja_add));
        LDSM4(bh[0], bB + sw_off(rb_base,      j0 + jb_add));
        LDSM4(bh[1], bB + sw_off(rb_base + 16, j0 + jb_add));
        #pragma unroll
        for (int mf = 0; mf < 2; mf++)
            #pragma unroll
            for (int bf = 0; bf < 2; bf++)
                #pragma unroll
                for (int h = 0; h < 2; h++)
                    MMA16816(c[mf * 4 + bf * 2 + h], a[mf],
                             bh[bf][2 * h], bh[bf][2 * h + 1]);
    }
}

// epilogue for tile nte from accumulators c -> pbuf
__device__ __forceinline__ void epi_tile(int nte, float (*c)[4], float* pbuf,
                                         const float* __restrict__ b1,
                                         const float* __restrict__ W2,
                                         const float* __restrict__ b2,
                                         int warp_m, int warp_n, int lane)
{
    const int q = lane >> 2, g = lane & 3;
    #pragma unroll
    for (int m = 0; m < 2; m++) {
        #pragma unroll
        for (int nd = 0; nd < 2; nd++) {
            float s0 = 0.f, s1 = 0.f;
            #pragma unroll
            for (int h = 0; h < 2; h++) {
                int f = m * 4 + nd * 2 + h;
                int gcol = nte * 128 + warp_n * 32 + (nd * 2 + h) * 8 + 2 * g;
                float bb0 = 0.f, ww0 = 0.f, bb1 = 0.f, ww1 = 0.f;
                if (gcol < N_INNER * HID) {
                    bb0 = __ldg(b1 + gcol);     ww0 = __ldg(W2 + gcol);
                    bb1 = __ldg(b1 + gcol + 1); ww1 = __ldg(W2 + gcol + 1);
                }
                s0 += fmaxf(c[f][0] + bb0, 0.f) * ww0 + fmaxf(c[f][1] + bb1, 0.f) * ww1;
                s1 += fmaxf(c[f][2] + bb0, 0.f) * ww0 + fmaxf(c[f][3] + bb1, 0.f) * ww1;
            }
            s0 += __shfl_xor_sync(0xffffffffu, s0, 1);
            s0 += __shfl_xor_sync(0xffffffffu, s0, 2);
            s1 += __shfl_xor_sync(0xffffffffu, s1, 1);
            s1 += __shfl_xor_sync(0xffffffffu, s1, 2);
            if (g == nd) {
                int nl = warp_n * 2 + nd;
                int ng = nte * 8 + nl;
                float b2v = (ng < N_INNER) ? __ldg(b2 + ng) : 0.f;
                int r0 = warp_m * 32 + m * 16 + q;
                pbuf[r0 * PSTR + ng]       = 1.f / (1.f + __expf(-(s0 + b2v)));
                pbuf[(r0 + 8) * PSTR + ng] = 1.f / (1.f + __expf(-(s1 + b2v)));
            }
        }
    }
}

__device__ __forceinline__ void pwrite_tile(int nte, const float* pbuf,
                                            float* outp, int row0, int tid)
{
    #pragma unroll
    for (int i2 = 0; i2 < 2; i2++) {
        int i = tid + i2 * GT;
        int r = i >> 3, cl = i & 7;
        int ng = nte * 8 + cl;
        if (ng < N_INNER)
            outp[(size_t)(row0 + r) * N_INNER + ng] = pbuf[r * PSTR + ng];
    }
}

__global__ __launch_bounds__(GT, 1)
void gemm_tree_kernel(const float* __restrict__ b1, const float* __restrict__ W2,
                      const float* __restrict__ b2, const float* __restrict__ leaf,
                      float* __restrict__ out)
{
    extern __shared__ char smem[];
    uint32_t sb = (uint32_t)__cvta_generic_to_shared(smem);
    float* pbuf = (float*)(smem + SM_P);

    const int tid    = threadIdx.x;
    const int lane   = tid & 31;
    const int wid    = tid >> 5;
    const int warp_m = wid & 3;
    const int warp_n = wid >> 2;
    const int row0   = blockIdx.x * MT;

    // G0: A + B tile0 (buf0) ; G1: B tile1 (buf1)
    load_tile(sb + SM_A, g_xh + (size_t)row0 * D_IN, tid);
    load_tile(sb + SM_B, g_wh, tid);
    CP_COMMIT();
    load_tile(sb + SM_B + 32768u, g_wh + (size_t)NTILE * D_IN, tid);
    CP_COMMIT();

    const int ra_base = warp_m * 32 + (lane & 7) + ((lane >> 3) & 1) * 8;
    const int ja_add  = lane >> 4;
    const int rb_base = warp_n * 32 + (lane & 7) + ((lane >> 4) & 1) * 8;
    const int jb_add  = (lane >> 3) & 1;

    float* outp = out + (size_t)BATCH * 257;

    float c0[8][4], c1[8][4];

    for (int nt = 0; nt < NT; nt += 2) {
        // ---- even tile nt: buf0 -> c0 ; epilogue tile nt-1 from c1 ----
        CP_WAIT1();
        __syncthreads();
        mma_tile(sb + SM_A, sb + SM_B, c0, ra_base, ja_add, rb_base, jb_add);
        if (nt > 0)
            epi_tile(nt - 1, c1, pbuf, b1, W2, b2, warp_m, warp_n, lane);
        __syncthreads();
        if (nt + 2 < NT) {
            load_tile(sb + SM_B, g_wh + (size_t)(nt + 2) * NTILE * D_IN, tid);
            CP_COMMIT();
        }
        if (nt > 0)
            pwrite_tile(nt - 1, pbuf, outp, row0, tid);

        // ---- odd tile nt+1: buf1 -> c1 ; epilogue tile nt from c0 ----
        if (nt + 2 < NT) { CP_WAIT1(); } else { CP_WAIT0(); }
        __syncthreads();
        mma_tile(sb + SM_A, sb + SM_B + 32768u, c1, ra_base, ja_add, rb_base, jb_add);
        epi_tile(nt, c0, pbuf, b1, W2, b2, warp_m, warp_n, lane);
        __syncthreads();
        if (nt + 3 < NT) {
            load_tile(sb + SM_B + 32768u, g_wh + (size_t)(nt + 3) * NTILE * D_IN, tid);
            CP_COMMIT();
        }
        pwrite_tile(nt, pbuf, outp, row0, tid);
    }

    // final epilogue: tile NT-1 from c1
    epi_tile(NT - 1, c1, pbuf, b1, W2, b2, warp_m, warp_n, lane);
    __syncthreads();
    pwrite_tile(NT - 1, pbuf, outp, row0, tid);

    // ================= fused tree pass =================
    __syncthreads();

    const float4* lf4 = (const float4*)(leaf + 8 * lane);
    const float4 l0 = lf4[0], l1 = lf4[1];

    #pragma unroll 1
    for (int rr = 0; rr < 8; rr++) {
        const int r   = wid * 8 + rr;
        const int row = row0 + r;
        const float* prow = pbuf + r * PSTR;
        float* nr = out + (size_t)BATCH * 512 + (size_t)row * N_INNER;
        float* pp = out + (size_t)BATCH + (size_t)row * N_LEAF;

        float pl[5];
        #pragma unroll
        for (int l = 0; l < 5; l++) {
            const int sz = 1 << l;
            pl[l] = (lane < sz) ? prow[sz - 1 + lane] : 0.f;
        }
        float p5  = prow[31 + lane];
        float p6a = prow[63 + 2 * lane];
        float p6b = prow[63 + 2 * lane + 1];
        float p7[4];
        #pragma unroll
        for (int j = 0; j < 4; j++) p7[j] = prow[127 + 4 * lane + j];

        float rv = (lane == 0) ? 1.f : 0.f;
        #pragma unroll
        for (int l = 0; l < 5; l++) {
            const int sz = 1 << l;
            if (lane < sz) nr[sz - 1 + lane] = rv;
            float rp = __shfl_sync(0xffffffffu, rv, lane >> 1);
            float pq = __shfl_sync(0xffffffffu, pl[l], lane >> 1);
            rv = (lane & 1) ? rp * pq : rp * (1.f - pq);
        }

        nr[31 + lane] = rv;
        float r6a = rv * (1.f - p5);
        float r6b = rv * p5;

        nr[63 + 2 * lane]     = r6a;
        nr[63 + 2 * lane + 1] = r6b;
        float r7[4] = { r6a * (1.f - p6a), r6a * p6a, r6b * (1.f - p6b), r6b * p6b };

        #pragma unroll
        for (int j = 0; j < 4; j++) nr[127 + 4 * lane + j] = r7[j];

        float r8[8];
        #pragma unroll
        for (int j = 0; j < 4; j++) {
            r8[2 * j]     = r7[j] * (1.f - p7[j]);
            r8[2 * j + 1] = r7[j] * p7[j];
        }
        float4* pp4 = (float4*)(pp + 8 * lane);
        pp4[0] = make_float4(r8[0], r8[1], r8[2], r8[3]);
        pp4[1] = make_float4(r8[4], r8[5], r8[6], r8[7]);

        float hs = r8[0] * l0.x + r8[1] * l0.y + r8[2] * l0.z + r8[3] * l0.w
                 + r8[4] * l1.x + r8[5] * l1.y + r8[6] * l1.z + r8[7] * l1.w;
        #pragma unroll
        for (int o = 16; o; o >>= 1) hs += __shfl_down_sync(0xffffffffu, hs, o);
        if (lane == 0) out[row] = hs;
    }
}

// ---------------- launch ----------------
extern "C" void kernel_launch(void* const* d_in, const int* in_sizes, int n_in,
                              void* d_out, int out_size)
{
    const float* x    = (const float*)d_in[0];
    const float* W1   = (const float*)d_in[1];
    const float* b1   = (const float*)d_in[2];
    const float* W2   = (const float*)d_in[3];
    const float* b2   = (const float*)d_in[4];
    const float* leaf = (const float*)d_in[5];
    float* out = (float*)d_out;

    cvt_x_kernel<<<(BATCH * D_IN) / 2048, 256>>>(x);
    cvt_w_kernel<<<256, 256>>>(W1);

    cudaFuncSetAttribute(gemm_tree_kernel, cudaFuncAttributeMaxDynamicSharedMemorySize, SMEM_TOTAL);
    gemm_tree_kernel<<<BATCH / MT, GT, SMEM_TOTAL>>>(b1, W2, b2, leaf, out);
}